// round 10
// baseline (speedup 1.0000x reference)
#include <cuda_runtime.h>
#include <cuda_bf16.h>

#define D 128
#define MAXN_NET 100000
#define MAXN_DAG 50000
#define MAXE_NET 600000
#define MAXE_DAG 400000

typedef unsigned long long u64;
typedef unsigned int u32;

// ---------------- device scratch (allocation-free rule: __device__ globals) ---
// All state is self-cleaning across graph replays:
//   dc     : zeroed by scan (this replay) before hist (next replay); zero at load
//   status : zeroed by reorder block 0 (this replay) for scan (next replay)
//   done   : reset by gather's last block
//   acc    : zeroed by gather's last block AFTER it consumes it (sole reader)
//   everything else is overwritten every replay
__device__ __align__(16) __nv_bfloat16 g_h_net[MAXN_NET * D];
__device__ __align__(16) __nv_bfloat16 g_h_dag[MAXN_DAG * D];
__device__ __align__(16) float2 g_dc_net[MAXN_NET];   // (sum ew, cnt) via RED
__device__ __align__(16) float2 g_dc_dag[MAXN_DAG];
__device__ float g_degf_net[MAXN_NET];                 // deg incl. self-loop
__device__ float g_degf_dag[MAXN_DAG];
__device__ int   g_rs_net[MAXN_NET];
__device__ int   g_rs_dag[MAXN_DAG];
__device__ int   g_cnt_net[MAXN_NET];
__device__ int   g_cnt_dag[MAXN_DAG];
__device__ int   g_ptr_net[MAXN_NET];
__device__ int   g_ptr_dag[MAXN_DAG];
__device__ __align__(16) int2 g_ed_net[MAXE_NET];     // (src, norm-as-int)
__device__ __align__(16) int2 g_ed_dag[MAXE_DAG];
__device__ u64   g_status_net[64];                    // lookback (value<<32)|flag
__device__ u64   g_status_dag[64];
__device__ int   g_done;
__device__ __align__(16) float g_acc[2 * D];

// ---------------- helpers ------------------------------------------------------
__device__ __forceinline__ u32 pack_bf16x2(float lo, float hi) {
    __nv_bfloat162 p = __float22bfloat162_rn(make_float2(lo, hi));
    return *reinterpret_cast<u32*>(&p);
}
__device__ __forceinline__ float4 bf16x4_to_f4(uint2 u) {
    __nv_bfloat162 p0 = *reinterpret_cast<__nv_bfloat162*>(&u.x);
    __nv_bfloat162 p1 = *reinterpret_cast<__nv_bfloat162*>(&u.y);
    float2 f0 = __bfloat1622float2(p0);
    float2 f1 = __bfloat1622float2(p1);
    return make_float4(f0.x, f0.y, f1.x, f1.y);
}
__device__ __forceinline__ u32 f2tf32(float f) {
    u32 r;
    asm("cvt.rna.tf32.f32 %0, %1;" : "=r"(r) : "f"(f));
    return r;
}
__device__ __forceinline__ uint4 f4_to_tf32x4(float4 v) {
    return make_uint4(f2tf32(v.x), f2tf32(v.y), f2tf32(v.z), f2tf32(v.w));
}
__device__ __forceinline__ void ldsm_x4(u32& r0, u32& r1, u32& r2, u32& r3, u32 a) {
    asm volatile("ldmatrix.sync.aligned.m8n8.x4.shared.b16 {%0,%1,%2,%3}, [%4];"
                 : "=r"(r0), "=r"(r1), "=r"(r2), "=r"(r3) : "r"(a));
}
__device__ __forceinline__ void mma_tf32(float c[4], u32 a0, u32 a1, u32 a2, u32 a3,
                                         u32 b0, u32 b1) {
    asm volatile(
        "mma.sync.aligned.m16n8k8.row.col.f32.tf32.tf32.f32 "
        "{%0,%1,%2,%3}, {%4,%5,%6,%7}, {%8,%9}, {%0,%1,%2,%3};"
        : "+f"(c[0]), "+f"(c[1]), "+f"(c[2]), "+f"(c[3])
        : "r"(a0), "r"(a1), "r"(a2), "r"(a3), "r"(b0), "r"(b1));
}
__device__ __forceinline__ void red_add_v2(float2* p, float a, float b) {
    asm volatile("red.global.add.v2.f32 [%0], {%1,%2};"
                 :: "l"(p), "f"(a), "f"(b) : "memory");
}

// ---------------- K1: histogram, one thread per edge, both graphs ---------------
__global__ void k_hist(const int* __restrict__ ei_n, const float* __restrict__ ew_n,
                       float2* __restrict__ dc_n, int En,
                       const int* __restrict__ ei_d, const float* __restrict__ ew_d,
                       float2* __restrict__ dc_d, int Ed) {
    int i = blockIdx.x * 256 + threadIdx.x;
    if (i < En) {
        red_add_v2(&dc_n[ei_n[En + i]], ew_n[i], 1.0f);
    } else if (i < En + Ed) {
        int e = i - En;
        red_add_v2(&dc_d[ei_d[Ed + e]], ew_d[e], 1.0f);
    }
}

// ---------------- K2: persistent TF32 GEMM, W loaded once per block -------------
// H[N,128] = X[N,128] @ W[128,128]; 64-row tiles; 296 blocks (2/SM) split
// between graphs. 256 thr = 8 warps (4 m x 2 n).
__global__ void __launch_bounds__(256, 2)
k_gemm(const float* __restrict__ Xn, const float* __restrict__ Wn,
       __nv_bfloat16* __restrict__ Hn, int Nn, int gNet,
       const float* __restrict__ Xd, const float* __restrict__ Wd,
       __nv_bfloat16* __restrict__ Hd, int Nd) {
    extern __shared__ char smem[];
    char* sA = smem;                 // 64 rows x 512B = 32KB
    char* sB = smem + 32 * 1024;     // 128 n-rows x 512B = 64KB (W transposed)
    const int tid = threadIdx.x;

    bool isNet = (int)blockIdx.x < gNet;
    const float* X = isNet ? Xn : Xd;
    const float* W = isNet ? Wn : Wd;
    __nv_bfloat16* Hb = isNet ? Hn : Hd;
    const int N = isNet ? Nn : Nd;
    const int blk = isNet ? blockIdx.x : blockIdx.x - gNet;
    const int nblk = isNet ? gNet : gridDim.x - gNet;
    const int tiles = (N + 63) / 64;

    // fill Wt once: transpose W[k][n] -> sB[n][k], coalesced over n
#pragma unroll
    for (int i = 0; i < 16; i++) {
        int idx = i * 256 + tid;
        int n = idx & 127, kc = idx >> 7;
        uint4 v = make_uint4(f2tf32(W[(kc * 4 + 0) * D + n]),
                             f2tf32(W[(kc * 4 + 1) * D + n]),
                             f2tf32(W[(kc * 4 + 2) * D + n]),
                             f2tf32(W[(kc * 4 + 3) * D + n]));
        *(uint4*)(sB + n * 512 + ((kc ^ (n & 7)) << 4)) = v;
    }
    __syncthreads();

    const int lane = tid & 31;
    const int w = tid >> 5;
    const int m0 = (w >> 1) * 16;
    const int n0 = (w & 1) * 64;
    const int sub = lane >> 3, rowin = lane & 7;

    for (int t = blk; t < tiles; t += nblk) {
        const int row0 = t * 64;
        // fill A tile (zero-pad past N)
#pragma unroll
        for (int i = 0; i < 8; i++) {
            int idx = i * 256 + tid;
            int r = idx >> 5, ch = idx & 31;
            int grow = row0 + r;
            float4 f = make_float4(0.f, 0.f, 0.f, 0.f);
            if (grow < N) f = ((const float4*)X)[grow * 32 + ch];
            *(uint4*)(sA + r * 512 + ((ch ^ (r & 7)) << 4)) = f4_to_tf32x4(f);
        }
        __syncthreads();

        float c[8][4];
#pragma unroll
        for (int nt = 0; nt < 8; nt++)
#pragma unroll
            for (int k = 0; k < 4; k++) c[nt][k] = 0.f;

#pragma unroll
        for (int ks = 0; ks < 16; ks++) {
            u32 a[4];
            {
                int r = m0 + (sub & 1) * 8 + rowin;
                int ch = ks * 2 + (sub >> 1);
                u32 addr = (u32)__cvta_generic_to_shared(
                    sA + r * 512 + ((ch ^ (r & 7)) << 4));
                ldsm_x4(a[0], a[1], a[2], a[3], addr);
            }
            u32 b[4][4];
#pragma unroll
            for (int q = 0; q < 4; q++) {
                int n = n0 + q * 16 + (sub >> 1) * 8 + rowin;
                int ch = ks * 2 + (sub & 1);
                u32 addr = (u32)__cvta_generic_to_shared(
                    sB + n * 512 + ((ch ^ (n & 7)) << 4));
                ldsm_x4(b[q][0], b[q][1], b[q][2], b[q][3], addr);
            }
#pragma unroll
            for (int nt = 0; nt < 8; nt++)
                mma_tf32(c[nt], a[0], a[1], a[2], a[3],
                         b[nt >> 1][(nt & 1) * 2], b[nt >> 1][(nt & 1) * 2 + 1]);
        }

#pragma unroll
        for (int nt = 0; nt < 8; nt++) {
            int r = m0 + (lane >> 2);
            int col = n0 + nt * 8 + (lane & 3) * 2;
            int g0 = row0 + r, g1 = g0 + 8;
            if (g0 < N)
                *(u32*)(Hb + (size_t)g0 * D + col) = pack_bf16x2(c[nt][0], c[nt][1]);
            if (g1 < N)
                *(u32*)(Hb + (size_t)g1 * D + col) = pack_bf16x2(c[nt][2], c[nt][3]);
        }
        __syncthreads();   // protect sA before next fill
    }
}

// ---------------- K3: single-pass scan + self-clean, both graphs ----------------
__global__ void k_scan(float2* __restrict__ dc_n, int* __restrict__ rs_n,
                       int* __restrict__ cnt_n, int* __restrict__ ptr_n,
                       float* __restrict__ degf_n, int Nn, int nbN,
                       float2* __restrict__ dc_d, int* __restrict__ rs_d,
                       int* __restrict__ cnt_d, int* __restrict__ ptr_d,
                       float* __restrict__ degf_d, int Nd,
                       u64* st_n, u64* st_d) {
    float2* dc; int* rs; int* cnto; int* ptr; float* degf; int N, blk;
    volatile u64* st;
    if ((int)blockIdx.x < nbN) {
        dc = dc_n; rs = rs_n; cnto = cnt_n; ptr = ptr_n; degf = degf_n;
        N = Nn; blk = blockIdx.x; st = (volatile u64*)st_n;
    } else {
        dc = dc_d; rs = rs_d; cnto = cnt_d; ptr = ptr_d; degf = degf_d;
        N = Nd; blk = blockIdx.x - nbN; st = (volatile u64*)st_d;
    }

    int t = threadIdx.x;
    int base = blk * 4096 + t * 16;
    int v[16], s = 0;
    float dx[16];
#pragma unroll
    for (int j = 0; j < 16; j++) {
        int idx = base + j;
        float2 d = (idx < N) ? dc[idx] : make_float2(0.f, 0.f);
        v[j] = (int)d.y;
        dx[j] = d.x;
        s += v[j];
    }
    int lane = t & 31, wid = t >> 5;
    int x = s;
#pragma unroll
    for (int o = 1; o < 32; o <<= 1) {
        int y = __shfl_up_sync(0xFFFFFFFFu, x, o);
        if (lane >= o) x += y;
    }
    __shared__ int wt[8];
    __shared__ int sprefix;
    if (lane == 31) wt[wid] = x;
    __syncthreads();
    if (t < 8) {
        int y = wt[t];
#pragma unroll
        for (int o = 1; o < 8; o <<= 1) {
            int z = __shfl_up_sync(0xFFu, y, o);
            if (t >= o) y += z;
        }
        wt[t] = y;
    }
    __syncthreads();
    int total = wt[7];
    int excl = x - s + (wid ? wt[wid - 1] : 0);

    if (t == 0) {
        if (blk == 0) { st[0] = ((u64)(u32)total << 32) | 2ull; sprefix = 0; }
        else          st[blk] = ((u64)(u32)total << 32) | 1ull;
    }
    if (blk > 0 && t < 32) {
        int running = 0;
        int end = blk;
        while (true) {
            int p = end - 1 - t;
            int f = 0, val = 0;
            if (p >= 0) {
                u64 pk;
                do { pk = st[p]; } while ((pk & 3ull) == 0ull);
                f = (int)(pk & 3ull);
                val = (int)(pk >> 32);
            }
            unsigned m2 = __ballot_sync(0xFFFFFFFFu, p >= 0 && f == 2);
            int contrib;
            bool fin;
            if (m2) {
                int l2 = __ffs(m2) - 1;
                contrib = (t <= l2 && p >= 0) ? val : 0;
                fin = true;
            } else {
                contrib = (p >= 0) ? val : 0;
                fin = false;
            }
#pragma unroll
            for (int o = 16; o; o >>= 1)
                contrib += __shfl_xor_sync(0xFFFFFFFFu, contrib, o);
            running += contrib;
            if (fin) break;
            end -= 32;
            if (end <= 0) break;
        }
        if (t == 0) {
            sprefix = running;
            st[blk] = ((u64)(u32)(running + total) << 32) | 2ull;
        }
    }
    __syncthreads();
    int run = sprefix + excl;
#pragma unroll
    for (int j = 0; j < 16; j++) {
        int idx = base + j;
        if (idx < N) {
            rs[idx] = run;
            cnto[idx] = v[j];
            ptr[idx] = run;
            degf[idx] = dx[j] + 1.0f;                // fold self-loop weight
            dc[idx] = make_float2(0.f, 0.f);         // self-clean for next replay
        }
        run += v[j];
    }
}

// ---------------- K4: reorder, one thread per edge; block 0 cleans status -------
__global__ void k_reorder(const int* __restrict__ ei_n, const float* __restrict__ ew_n,
                          const float* __restrict__ degf_n, int* __restrict__ ptr_n,
                          int2* __restrict__ ed_n, int En,
                          const int* __restrict__ ei_d, const float* __restrict__ ew_d,
                          const float* __restrict__ degf_d, int* __restrict__ ptr_d,
                          int2* __restrict__ ed_d, int Ed,
                          u64* st_n, u64* st_d) {
    if (blockIdx.x == 0 && threadIdx.x < 128) {     // clean lookback state
        if (threadIdx.x < 64) st_n[threadIdx.x] = 0ull;
        else                  st_d[threadIdx.x - 64] = 0ull;
    }
    int i = blockIdx.x * 256 + threadIdx.x;
    const int* ei; const float* ew; const float* degf; int* ptr; int2* ed; int E, e;
    if (i < En)            { ei = ei_n; ew = ew_n; degf = degf_n; ptr = ptr_n; ed = ed_n; E = En; e = i; }
    else if (i < En + Ed)  { ei = ei_d; ew = ew_d; degf = degf_d; ptr = ptr_d; ed = ed_d; E = Ed; e = i - En; }
    else return;
    int src = ei[e];
    int dst = ei[E + e];
    float nm = rsqrtf(degf[src]) * ew[e] * rsqrtf(degf[dst]);
    int p = atomicAdd(&ptr[dst], 1);
    ed[p] = make_int2(src, __float_as_int(nm));
}

// ---------------- K5: gather + epilogue + (last block) final MLP ----------------
__global__ void gather_kernel(const int* __restrict__ rs_n, const int* __restrict__ cnt_n,
                              const int2* __restrict__ ed_n,
                              const __nv_bfloat16* __restrict__ Hn,
                              const float* __restrict__ degf_n,
                              const float* __restrict__ b_n, int Nn, int blocksNet,
                              const int* __restrict__ rs_d, const int* __restrict__ cnt_d,
                              const int2* __restrict__ ed_d,
                              const __nv_bfloat16* __restrict__ Hd,
                              const float* __restrict__ degf_d,
                              const float* __restrict__ b_d,  int Nd,
                              float* __restrict__ acc, int* __restrict__ done,
                              const float* __restrict__ W1, const float* __restrict__ b1,
                              const float* __restrict__ W2, const float* __restrict__ b2,
                              float invNnet, float invNdag, float* __restrict__ out) {
    bool isNet = (int)blockIdx.x < blocksNet;
    const int* rs   = isNet ? rs_n  : rs_d;
    const int* cnt  = isNet ? cnt_n : cnt_d;
    const int2* ed  = isNet ? ed_n  : ed_d;
    const __nv_bfloat16* H = isNet ? Hn : Hd;
    const float* degf = isNet ? degf_n : degf_d;
    const float* bia = isNet ? b_n : b_d;
    int N = isNet ? Nn : Nd;
    float* accBase = isNet ? acc : acc + D;
    int blk  = isNet ? blockIdx.x : blockIdx.x - blocksNet;
    int nblk = isNet ? blocksNet : gridDim.x - blocksNet;

    __shared__ float sacc[D];
    __shared__ int slast;
    int t = threadIdx.x;
    if (t < D) sacc[t] = 0.f;
    __syncthreads();

    int lane = t & 31;
    int warp = blk * 8 + (t >> 5);
    int nwarps = nblk * 8;
    float4 bb = ((const float4*)bia)[lane];
    float4 macc = make_float4(0.f, 0.f, 0.f, 0.f);

    for (int i = warp; i < N; i += nwarps) {
        float dd = 1.0f / degf[i];                   // = dinv^2 (self-loop)
        float4 v = bf16x4_to_f4(((const uint2*)(H + (size_t)i * D))[lane]);
        v.x *= dd; v.y *= dd; v.z *= dd; v.w *= dd;
        int s = rs[i];
        int c = cnt[i];
        int j = 0;
        if (c >= 4) {                                 // pipelined 4-edge batches
            int2 e0 = __ldg(&ed[s + 0]);
            int2 e1 = __ldg(&ed[s + 1]);
            int2 e2 = __ldg(&ed[s + 2]);
            int2 e3 = __ldg(&ed[s + 3]);
            while (true) {
                float4 h0 = bf16x4_to_f4(((const uint2*)(H + (size_t)e0.x * D))[lane]);
                float4 h1 = bf16x4_to_f4(((const uint2*)(H + (size_t)e1.x * D))[lane]);
                float4 h2 = bf16x4_to_f4(((const uint2*)(H + (size_t)e2.x * D))[lane]);
                float4 h3 = bf16x4_to_f4(((const uint2*)(H + (size_t)e3.x * D))[lane]);
                float n0 = __int_as_float(e0.y), n1 = __int_as_float(e1.y);
                float n2 = __int_as_float(e2.y), n3 = __int_as_float(e3.y);
                int jn = j + 4;
                bool more = (jn + 4 <= c);
                if (more) {                           // prefetch next batch
                    e0 = __ldg(&ed[s + jn + 0]);
                    e1 = __ldg(&ed[s + jn + 1]);
                    e2 = __ldg(&ed[s + jn + 2]);
                    e3 = __ldg(&ed[s + jn + 3]);
                }
                v.x += n0 * h0.x + n1 * h1.x + n2 * h2.x + n3 * h3.x;
                v.y += n0 * h0.y + n1 * h1.y + n2 * h2.y + n3 * h3.y;
                v.z += n0 * h0.z + n1 * h1.z + n2 * h2.z + n3 * h3.z;
                v.w += n0 * h0.w + n1 * h1.w + n2 * h2.w + n3 * h3.w;
                j = jn;
                if (!more) break;
            }
        }
        if (j + 2 <= c) {
            int2 e0 = __ldg(&ed[s + j]);
            int2 e1 = __ldg(&ed[s + j + 1]);
            float4 h0 = bf16x4_to_f4(((const uint2*)(H + (size_t)e0.x * D))[lane]);
            float4 h1 = bf16x4_to_f4(((const uint2*)(H + (size_t)e1.x * D))[lane]);
            float n0 = __int_as_float(e0.y), n1 = __int_as_float(e1.y);
            v.x += n0 * h0.x + n1 * h1.x;
            v.y += n0 * h0.y + n1 * h1.y;
            v.z += n0 * h0.z + n1 * h1.z;
            v.w += n0 * h0.w + n1 * h1.w;
            j += 2;
        }
        if (j < c) {
            int2 e = __ldg(&ed[s + j]);
            float nm = __int_as_float(e.y);
            float4 hh = bf16x4_to_f4(((const uint2*)(H + (size_t)e.x * D))[lane]);
            v.x += nm * hh.x; v.y += nm * hh.y;
            v.z += nm * hh.z; v.w += nm * hh.w;
        }
        v.x = fmaxf(v.x + bb.x, 0.f);
        v.y = fmaxf(v.y + bb.y, 0.f);
        v.z = fmaxf(v.z + bb.z, 0.f);
        v.w = fmaxf(v.w + bb.w, 0.f);
        float ss = v.x * v.x + v.y * v.y + v.z * v.z + v.w * v.w;
#pragma unroll
        for (int o = 16; o; o >>= 1) ss += __shfl_xor_sync(0xFFFFFFFFu, ss, o);
        float scale = 1.0f / fmaxf(sqrtf(ss), 1e-12f);
        macc.x += v.x * scale;
        macc.y += v.y * scale;
        macc.z += v.z * scale;
        macc.w += v.w * scale;
    }
    float* so = sacc + lane * 4;
    atomicAdd(so + 0, macc.x);
    atomicAdd(so + 1, macc.y);
    atomicAdd(so + 2, macc.z);
    atomicAdd(so + 3, macc.w);
    __syncthreads();
    if (t < D) atomicAdd(accBase + t, sacc[t]);

    // ---- last block: final MLP; consumes acc then zeroes it for next replay ----
    __syncthreads();
    if (t == 0) {
        __threadfence();
        slast = (atomicAdd(done, 1) == (int)gridDim.x - 1);
    }
    __syncthreads();
    if (slast) {
        __threadfence();
        __shared__ float cvec[256];
        __shared__ float h1[64];
        cvec[t] = __ldcg(&acc[t]) * (t < 128 ? invNnet : invNdag);
        __syncthreads();
        acc[t] = 0.f;                                 // self-clean (sole reader)
        if (t < 64) {
            float s = b1[t];
#pragma unroll 8
            for (int i = 0; i < 256; i++) s += cvec[i] * W1[i * 64 + t];
            h1[t] = fmaxf(s, 0.f);
        }
        __syncthreads();
        if (t == 0) {
            float s = b2[0];
#pragma unroll
            for (int j = 0; j < 64; j++) s += h1[j] * W2[j];
            out[0] = s;
            *done = 0;                                // self-clean
        }
    }
}

// ---------------- launch ----------------------------------------------------------
extern "C" void kernel_launch(void* const* d_in, const int* in_sizes, int n_in,
                              void* d_out, int out_size) {
    const float* net_feat = (const float*)d_in[0];
    const int*   net_ei   = (const int*)  d_in[1];
    const float* net_ew   = (const float*)d_in[2];
    const float* dag_feat = (const float*)d_in[3];
    const int*   dag_ei   = (const int*)  d_in[4];
    const float* dag_ew   = (const float*)d_in[5];
    const float* W_net    = (const float*)d_in[6];
    const float* b_net    = (const float*)d_in[7];
    const float* W_dag    = (const float*)d_in[8];
    const float* b_dag    = (const float*)d_in[9];
    const float* W1       = (const float*)d_in[10];
    const float* b1       = (const float*)d_in[11];
    const float* W2       = (const float*)d_in[12];
    const float* b2       = (const float*)d_in[13];
    float* out = (float*)d_out;

    const int N_net = in_sizes[0] / D;
    const int E_net = in_sizes[2];
    const int N_dag = in_sizes[3] / D;
    const int E_dag = in_sizes[5];

    void *p;
    cudaGetSymbolAddress(&p, g_h_net);    __nv_bfloat16* h_net = (__nv_bfloat16*)p;
    cudaGetSymbolAddress(&p, g_h_dag);    __nv_bfloat16* h_dag = (__nv_bfloat16*)p;
    cudaGetSymbolAddress(&p, g_dc_net);   float2* dc_net = (float2*)p;
    cudaGetSymbolAddress(&p, g_dc_dag);   float2* dc_dag = (float2*)p;
    cudaGetSymbolAddress(&p, g_degf_net); float* degf_net = (float*)p;
    cudaGetSymbolAddress(&p, g_degf_dag); float* degf_dag = (float*)p;
    cudaGetSymbolAddress(&p, g_rs_net);   int* rs_net = (int*)p;
    cudaGetSymbolAddress(&p, g_rs_dag);   int* rs_dag = (int*)p;
    cudaGetSymbolAddress(&p, g_cnt_net);  int* cnt_net = (int*)p;
    cudaGetSymbolAddress(&p, g_cnt_dag);  int* cnt_dag = (int*)p;
    cudaGetSymbolAddress(&p, g_ptr_net);  int* ptr_net = (int*)p;
    cudaGetSymbolAddress(&p, g_ptr_dag);  int* ptr_dag = (int*)p;
    cudaGetSymbolAddress(&p, g_ed_net);   int2* ed_net = (int2*)p;
    cudaGetSymbolAddress(&p, g_ed_dag);   int2* ed_dag = (int2*)p;
    cudaGetSymbolAddress(&p, g_status_net); u64* st_net = (u64*)p;
    cudaGetSymbolAddress(&p, g_status_dag); u64* st_dag = (u64*)p;
    cudaGetSymbolAddress(&p, g_done);     int* done = (int*)p;
    cudaGetSymbolAddress(&p, g_acc);      float* acc = (float*)p;

    const int smem_gemm = 96 * 1024;
    cudaFuncSetAttribute(k_gemm,
                         cudaFuncAttributeMaxDynamicSharedMemorySize, smem_gemm);

    const int nbN = (N_net + 4095) / 4096;
    const int nbD = (N_dag + 4095) / 4096;
    const int edgeBlocks = (E_net + E_dag + 255) / 256;

    // K1: histogram (full occupancy, one thread per edge)
    k_hist<<<edgeBlocks, 256>>>(net_ei, net_ew, dc_net, E_net,
                                dag_ei, dag_ew, dc_dag, E_dag);

    // K2: persistent GEMM, both graphs (W amortized across ~8 tiles/block)
    const int gTotal = 296;
    const int gNet = (int)((long long)gTotal * ((N_net + 63) / 64) /
                           (((N_net + 63) / 64) + ((N_dag + 63) / 64)));
    k_gemm<<<gTotal, 256, smem_gemm>>>(net_feat, W_net, h_net, N_net, gNet,
                                       dag_feat, W_dag, h_dag, N_dag);

    // K3: single-pass scan (self-cleans dc, emits degf)
    k_scan<<<nbN + nbD, 256>>>(dc_net, rs_net, cnt_net, ptr_net, degf_net, N_net, nbN,
                               dc_dag, rs_dag, cnt_dag, ptr_dag, degf_dag, N_dag,
                               st_net, st_dag);

    // K4: reorder (full occupancy, one thread per edge; cleans status words)
    k_reorder<<<edgeBlocks, 256>>>(net_ei, net_ew, degf_net, ptr_net, ed_net, E_net,
                                   dag_ei, dag_ew, degf_dag, ptr_dag, ed_dag, E_dag,
                                   st_net, st_dag);

    // K5: gather + epilogue + final MLP
    const int blocksNet = 540, blocksDag = 348;
    gather_kernel<<<blocksNet + blocksDag, 256>>>(
        rs_net, cnt_net, ed_net, h_net, degf_net, b_net, N_net, blocksNet,
        rs_dag, cnt_dag, ed_dag, h_dag, degf_dag, b_dag, N_dag, acc, done,
        W1, b1, W2, b2, 1.0f / (float)N_net, 1.0f / (float)N_dag, out);
}

// round 11
// speedup vs baseline: 1.3619x; 1.3619x over previous
#include <cuda_runtime.h>
#include <cuda_bf16.h>

#define D 128
#define MAXN_NET 100000
#define MAXN_DAG 50000
#define MAXE_NET 600000
#define MAXE_DAG 400000

typedef unsigned long long u64;
typedef unsigned int u32;

// ---------------- device scratch (allocation-free rule: __device__ globals) ---
// Self-cleaning across graph replays:
//   dc     : zeroed by scan (this replay) before hist (next replay); zero at load
//   status : zeroed by K3 block 0 (this replay) for scan (next replay)
//   done   : reset by gather's last block
//   acc    : zeroed by gather's last block AFTER consuming it (sole reader)
__device__ __align__(16) __nv_bfloat16 g_h_net[MAXN_NET * D];
__device__ __align__(16) __nv_bfloat16 g_h_dag[MAXN_DAG * D];
__device__ __align__(16) float2 g_dc_net[MAXN_NET];   // (sum ew, cnt) via RED
__device__ __align__(16) float2 g_dc_dag[MAXN_DAG];
__device__ float g_dinv_net[MAXN_NET];                 // rsqrt(deg incl self-loop)
__device__ float g_dinv_dag[MAXN_DAG];
__device__ int   g_rs_net[MAXN_NET];
__device__ int   g_rs_dag[MAXN_DAG];
__device__ int   g_cnt_net[MAXN_NET];
__device__ int   g_cnt_dag[MAXN_DAG];
__device__ int   g_ptr_net[MAXN_NET];
__device__ int   g_ptr_dag[MAXN_DAG];
__device__ __align__(16) int2 g_ed_net[MAXE_NET];     // (src, dinv[src]*ew as int)
__device__ __align__(16) int2 g_ed_dag[MAXE_DAG];
__device__ u64   g_status_net[64];                    // lookback (value<<32)|flag
__device__ u64   g_status_dag[64];
__device__ int   g_done;
__device__ __align__(16) float g_acc[2 * D];

// ---------------- helpers ------------------------------------------------------
__device__ __forceinline__ u32 pack_bf16x2(float lo, float hi) {
    __nv_bfloat162 p = __float22bfloat162_rn(make_float2(lo, hi));
    return *reinterpret_cast<u32*>(&p);
}
__device__ __forceinline__ float4 bf16x4_to_f4(uint2 u) {
    __nv_bfloat162 p0 = *reinterpret_cast<__nv_bfloat162*>(&u.x);
    __nv_bfloat162 p1 = *reinterpret_cast<__nv_bfloat162*>(&u.y);
    float2 f0 = __bfloat1622float2(p0);
    float2 f1 = __bfloat1622float2(p1);
    return make_float4(f0.x, f0.y, f1.x, f1.y);
}
__device__ __forceinline__ u32 f2tf32(float f) {
    u32 r;
    asm("cvt.rna.tf32.f32 %0, %1;" : "=r"(r) : "f"(f));
    return r;
}
__device__ __forceinline__ uint4 f4_to_tf32x4(float4 v) {
    return make_uint4(f2tf32(v.x), f2tf32(v.y), f2tf32(v.z), f2tf32(v.w));
}
__device__ __forceinline__ void ldsm_x4(u32& r0, u32& r1, u32& r2, u32& r3, u32 a) {
    asm volatile("ldmatrix.sync.aligned.m8n8.x4.shared.b16 {%0,%1,%2,%3}, [%4];"
                 : "=r"(r0), "=r"(r1), "=r"(r2), "=r"(r3) : "r"(a));
}
__device__ __forceinline__ void mma_tf32(float c[4], u32 a0, u32 a1, u32 a2, u32 a3,
                                         u32 b0, u32 b1) {
    asm volatile(
        "mma.sync.aligned.m16n8k8.row.col.f32.tf32.tf32.f32 "
        "{%0,%1,%2,%3}, {%4,%5,%6,%7}, {%8,%9}, {%0,%1,%2,%3};"
        : "+f"(c[0]), "+f"(c[1]), "+f"(c[2]), "+f"(c[3])
        : "r"(a0), "r"(a1), "r"(a2), "r"(a3), "r"(b0), "r"(b1));
}
__device__ __forceinline__ void red_add_v2(float2* p, float a, float b) {
    asm volatile("red.global.add.v2.f32 [%0], {%1,%2};"
                 :: "l"(p), "f"(a), "f"(b) : "memory");
}

// ---------------- TF32 GEMM body: 64-row tile (96KB smem, 2 blocks/SM) ---------
__device__ void gemm_body(const float* __restrict__ X, const float* __restrict__ W,
                          __nv_bfloat16* __restrict__ Hb, int N, int bid) {
    extern __shared__ char smem[];
    char* sA = smem;                 // 64 rows x 512B = 32KB
    char* sB = smem + 32 * 1024;     // 128 n-rows x 512B = 64KB (W transposed)
    const int tid = threadIdx.x;
    const int row0 = bid * 64;

    // fill Wt: transpose W[k][n] -> sB[n][k], coalesced over n
#pragma unroll
    for (int i = 0; i < 16; i++) {
        int idx = i * 256 + tid;
        int n = idx & 127, kc = idx >> 7;
        uint4 v = make_uint4(f2tf32(W[(kc * 4 + 0) * D + n]),
                             f2tf32(W[(kc * 4 + 1) * D + n]),
                             f2tf32(W[(kc * 4 + 2) * D + n]),
                             f2tf32(W[(kc * 4 + 3) * D + n]));
        *(uint4*)(sB + n * 512 + ((kc ^ (n & 7)) << 4)) = v;
    }
    // fill A (64 X rows, zero-pad past N)
#pragma unroll
    for (int i = 0; i < 8; i++) {
        int idx = i * 256 + tid;
        int r = idx >> 5, ch = idx & 31;
        int grow = row0 + r;
        float4 f = make_float4(0.f, 0.f, 0.f, 0.f);
        if (grow < N) f = ((const float4*)X)[grow * 32 + ch];
        *(uint4*)(sA + r * 512 + ((ch ^ (r & 7)) << 4)) = f4_to_tf32x4(f);
    }
    __syncthreads();

    const int lane = tid & 31;
    const int w = tid >> 5;
    const int m0 = (w >> 1) * 16;
    const int n0 = (w & 1) * 64;
    const int sub = lane >> 3, rowin = lane & 7;

    float c[8][4];
#pragma unroll
    for (int nt = 0; nt < 8; nt++)
#pragma unroll
        for (int k = 0; k < 4; k++) c[nt][k] = 0.f;

#pragma unroll
    for (int ks = 0; ks < 16; ks++) {
        u32 a[4];
        {
            int r = m0 + (sub & 1) * 8 + rowin;
            int ch = ks * 2 + (sub >> 1);
            u32 addr = (u32)__cvta_generic_to_shared(
                sA + r * 512 + ((ch ^ (r & 7)) << 4));
            ldsm_x4(a[0], a[1], a[2], a[3], addr);
        }
        u32 b[4][4];
#pragma unroll
        for (int q = 0; q < 4; q++) {
            int n = n0 + q * 16 + (sub >> 1) * 8 + rowin;
            int ch = ks * 2 + (sub & 1);
            u32 addr = (u32)__cvta_generic_to_shared(
                sB + n * 512 + ((ch ^ (n & 7)) << 4));
            ldsm_x4(b[q][0], b[q][1], b[q][2], b[q][3], addr);
        }
#pragma unroll
        for (int nt = 0; nt < 8; nt++)
            mma_tf32(c[nt], a[0], a[1], a[2], a[3],
                     b[nt >> 1][(nt & 1) * 2], b[nt >> 1][(nt & 1) * 2 + 1]);
    }

#pragma unroll
    for (int nt = 0; nt < 8; nt++) {
        int r = m0 + (lane >> 2);
        int col = n0 + nt * 8 + (lane & 3) * 2;
        int g0 = row0 + r, g1 = g0 + 8;
        if (g0 < N)
            *(u32*)(Hb + (size_t)g0 * D + col) = pack_bf16x2(c[nt][0], c[nt][1]);
        if (g1 < N)
            *(u32*)(Hb + (size_t)g1 * D + col) = pack_bf16x2(c[nt][2], c[nt][3]);
    }
}

// ---------------- K1: hist(both) + GEMM(net), overlapped -----------------------
__global__ void __launch_bounds__(256, 2)
k_hist_gemmnet(const int* __restrict__ ei_n, const float* __restrict__ ew_n,
               float2* __restrict__ dc_n, int En,
               const int* __restrict__ ei_d, const float* __restrict__ ew_d,
               float2* __restrict__ dc_d, int Ed,
               int histBlocks,
               const float* __restrict__ X, const float* __restrict__ W,
               __nv_bfloat16* __restrict__ Hb, int N) {
    if ((int)blockIdx.x < histBlocks) {
        int stride = histBlocks * 256;
        int total = En + Ed;
        for (int i = blockIdx.x * 256 + threadIdx.x; i < total; i += stride) {
            if (i < En) {
                red_add_v2(&dc_n[ei_n[En + i]], ew_n[i], 1.0f);
            } else {
                int e = i - En;
                red_add_v2(&dc_d[ei_d[Ed + e]], ew_d[e], 1.0f);
            }
        }
    } else {
        gemm_body(X, W, Hb, N, blockIdx.x - histBlocks);
    }
}

// ---------------- K2: single-pass scan; emits dinv; self-cleans dc --------------
__global__ void k_scan(float2* __restrict__ dc_n, int* __restrict__ rs_n,
                       int* __restrict__ cnt_n, int* __restrict__ ptr_n,
                       float* __restrict__ dinv_n, int Nn, int nbN,
                       float2* __restrict__ dc_d, int* __restrict__ rs_d,
                       int* __restrict__ cnt_d, int* __restrict__ ptr_d,
                       float* __restrict__ dinv_d, int Nd,
                       u64* st_n, u64* st_d) {
    float2* dc; int* rs; int* cnto; int* ptr; float* dinv; int N, blk;
    volatile u64* st;
    if ((int)blockIdx.x < nbN) {
        dc = dc_n; rs = rs_n; cnto = cnt_n; ptr = ptr_n; dinv = dinv_n;
        N = Nn; blk = blockIdx.x; st = (volatile u64*)st_n;
    } else {
        dc = dc_d; rs = rs_d; cnto = cnt_d; ptr = ptr_d; dinv = dinv_d;
        N = Nd; blk = blockIdx.x - nbN; st = (volatile u64*)st_d;
    }

    int t = threadIdx.x;
    int base = blk * 4096 + t * 16;
    int v[16], s = 0;
    float dx[16];
#pragma unroll
    for (int j = 0; j < 16; j++) {
        int idx = base + j;
        float2 d = (idx < N) ? dc[idx] : make_float2(0.f, 0.f);
        v[j] = (int)d.y;
        dx[j] = d.x;
        s += v[j];
    }
    int lane = t & 31, wid = t >> 5;
    int x = s;
#pragma unroll
    for (int o = 1; o < 32; o <<= 1) {
        int y = __shfl_up_sync(0xFFFFFFFFu, x, o);
        if (lane >= o) x += y;
    }
    __shared__ int wt[8];
    __shared__ int sprefix;
    if (lane == 31) wt[wid] = x;
    __syncthreads();
    if (t < 8) {
        int y = wt[t];
#pragma unroll
        for (int o = 1; o < 8; o <<= 1) {
            int z = __shfl_up_sync(0xFFu, y, o);
            if (t >= o) y += z;
        }
        wt[t] = y;
    }
    __syncthreads();
    int total = wt[7];
    int excl = x - s + (wid ? wt[wid - 1] : 0);

    if (t == 0) {
        if (blk == 0) { st[0] = ((u64)(u32)total << 32) | 2ull; sprefix = 0; }
        else          st[blk] = ((u64)(u32)total << 32) | 1ull;
    }
    if (blk > 0 && t < 32) {
        int running = 0;
        int end = blk;
        while (true) {
            int p = end - 1 - t;
            int f = 0, val = 0;
            if (p >= 0) {
                u64 pk;
                do { pk = st[p]; } while ((pk & 3ull) == 0ull);
                f = (int)(pk & 3ull);
                val = (int)(pk >> 32);
            }
            unsigned m2 = __ballot_sync(0xFFFFFFFFu, p >= 0 && f == 2);
            int contrib;
            bool fin;
            if (m2) {
                int l2 = __ffs(m2) - 1;
                contrib = (t <= l2 && p >= 0) ? val : 0;
                fin = true;
            } else {
                contrib = (p >= 0) ? val : 0;
                fin = false;
            }
#pragma unroll
            for (int o = 16; o; o >>= 1)
                contrib += __shfl_xor_sync(0xFFFFFFFFu, contrib, o);
            running += contrib;
            if (fin) break;
            end -= 32;
            if (end <= 0) break;
        }
        if (t == 0) {
            sprefix = running;
            st[blk] = ((u64)(u32)(running + total) << 32) | 2ull;
        }
    }
    __syncthreads();
    int run = sprefix + excl;
#pragma unroll
    for (int j = 0; j < 16; j++) {
        int idx = base + j;
        if (idx < N) {
            rs[idx] = run;
            cnto[idx] = v[j];
            ptr[idx] = run;
            dinv[idx] = rsqrtf(dx[j] + 1.0f);          // self-loop folded
            dc[idx] = make_float2(0.f, 0.f);           // self-clean
        }
        run += v[j];
    }
}

// ---------------- K3: reorder(both, slim) + GEMM(dag), overlapped ---------------
__global__ void __launch_bounds__(256, 2)
k_reorder_gemmdag(const int* __restrict__ ei_n, const float* __restrict__ ew_n,
                  const float* __restrict__ dinv_n, int* __restrict__ ptr_n,
                  int2* __restrict__ ed_n, int En,
                  const int* __restrict__ ei_d, const float* __restrict__ ew_d,
                  const float* __restrict__ dinv_d, int* __restrict__ ptr_d,
                  int2* __restrict__ ed_d, int Ed,
                  int reorderBlocks,
                  const float* __restrict__ X, const float* __restrict__ W,
                  __nv_bfloat16* __restrict__ Hb, int N,
                  u64* st_n, u64* st_d) {
    if ((int)blockIdx.x < reorderBlocks) {
        if (blockIdx.x == 0 && threadIdx.x < 128) {    // clean lookback state
            if (threadIdx.x < 64) st_n[threadIdx.x] = 0ull;
            else                  st_d[threadIdx.x - 64] = 0ull;
        }
        int stride = reorderBlocks * 256;
        int total = En + Ed;
        for (int i = blockIdx.x * 256 + threadIdx.x; i < total; i += stride) {
            const int* ei; const float* ew; const float* dinv; int* ptr;
            int2* ed; int E, e;
            if (i < En) { ei = ei_n; ew = ew_n; dinv = dinv_n; ptr = ptr_n; ed = ed_n; E = En; e = i; }
            else        { ei = ei_d; ew = ew_d; dinv = dinv_d; ptr = ptr_d; ed = ed_d; E = Ed; e = i - En; }
            int src = ei[e];
            int dst = ei[E + e];
            float nm = dinv[src] * ew[e];              // dst factor applied in gather
            int p = atomicAdd(&ptr[dst], 1);
            ed[p] = make_int2(src, __float_as_int(nm));
        }
    } else {
        gemm_body(X, W, Hb, N, blockIdx.x - reorderBlocks);
    }
}

// ---------------- K4: gather + epilogue + (last block) final MLP ----------------
__global__ void gather_kernel(const int* __restrict__ rs_n, const int* __restrict__ cnt_n,
                              const int2* __restrict__ ed_n,
                              const __nv_bfloat16* __restrict__ Hn,
                              const float* __restrict__ dinv_n,
                              const float* __restrict__ b_n, int Nn, int blocksNet,
                              const int* __restrict__ rs_d, const int* __restrict__ cnt_d,
                              const int2* __restrict__ ed_d,
                              const __nv_bfloat16* __restrict__ Hd,
                              const float* __restrict__ dinv_d,
                              const float* __restrict__ b_d,  int Nd,
                              float* __restrict__ acc, int* __restrict__ done,
                              const float* __restrict__ W1, const float* __restrict__ b1,
                              const float* __restrict__ W2, const float* __restrict__ b2,
                              float invNnet, float invNdag, float* __restrict__ out) {
    bool isNet = (int)blockIdx.x < blocksNet;
    const int* rs   = isNet ? rs_n  : rs_d;
    const int* cnt  = isNet ? cnt_n : cnt_d;
    const int2* ed  = isNet ? ed_n  : ed_d;
    const __nv_bfloat16* H = isNet ? Hn : Hd;
    const float* dinv = isNet ? dinv_n : dinv_d;
    const float* bia = isNet ? b_n : b_d;
    int N = isNet ? Nn : Nd;
    float* accBase = isNet ? acc : acc + D;
    int blk  = isNet ? blockIdx.x : blockIdx.x - blocksNet;
    int nblk = isNet ? blocksNet : gridDim.x - blocksNet;

    __shared__ float sacc[D];
    __shared__ int slast;
    int t = threadIdx.x;
    if (t < D) sacc[t] = 0.f;
    __syncthreads();

    int lane = t & 31;
    int warp = blk * 8 + (t >> 5);
    int nwarps = nblk * 8;
    float4 bb = ((const float4*)bia)[lane];
    float4 macc = make_float4(0.f, 0.f, 0.f, 0.f);

    for (int i = warp; i < N; i += nwarps) {
        float di = dinv[i];
        // v accumulates di*h_i + sum(nm_e * h_src); final scale by di.
        float4 v = bf16x4_to_f4(((const uint2*)(H + (size_t)i * D))[lane]);
        v.x *= di; v.y *= di; v.z *= di; v.w *= di;
        int s = rs[i];
        int c = cnt[i];
        int j = 0;
        if (c >= 4) {                                 // pipelined 4-edge batches
            int2 e0 = __ldg(&ed[s + 0]);
            int2 e1 = __ldg(&ed[s + 1]);
            int2 e2 = __ldg(&ed[s + 2]);
            int2 e3 = __ldg(&ed[s + 3]);
            while (true) {
                float4 h0 = bf16x4_to_f4(((const uint2*)(H + (size_t)e0.x * D))[lane]);
                float4 h1 = bf16x4_to_f4(((const uint2*)(H + (size_t)e1.x * D))[lane]);
                float4 h2 = bf16x4_to_f4(((const uint2*)(H + (size_t)e2.x * D))[lane]);
                float4 h3 = bf16x4_to_f4(((const uint2*)(H + (size_t)e3.x * D))[lane]);
                float n0 = __int_as_float(e0.y), n1 = __int_as_float(e1.y);
                float n2 = __int_as_float(e2.y), n3 = __int_as_float(e3.y);
                int jn = j + 4;
                bool more = (jn + 4 <= c);
                if (more) {                           // prefetch next batch
                    e0 = __ldg(&ed[s + jn + 0]);
                    e1 = __ldg(&ed[s + jn + 1]);
                    e2 = __ldg(&ed[s + jn + 2]);
                    e3 = __ldg(&ed[s + jn + 3]);
                }
                v.x += n0 * h0.x + n1 * h1.x + n2 * h2.x + n3 * h3.x;
                v.y += n0 * h0.y + n1 * h1.y + n2 * h2.y + n3 * h3.y;
                v.z += n0 * h0.z + n1 * h1.z + n2 * h2.z + n3 * h3.z;
                v.w += n0 * h0.w + n1 * h1.w + n2 * h2.w + n3 * h3.w;
                j = jn;
                if (!more) break;
            }
        }
        if (j + 2 <= c) {
            int2 e0 = __ldg(&ed[s + j]);
            int2 e1 = __ldg(&ed[s + j + 1]);
            float4 h0 = bf16x4_to_f4(((const uint2*)(H + (size_t)e0.x * D))[lane]);
            float4 h1 = bf16x4_to_f4(((const uint2*)(H + (size_t)e1.x * D))[lane]);
            float n0 = __int_as_float(e0.y), n1 = __int_as_float(e1.y);
            v.x += n0 * h0.x + n1 * h1.x;
            v.y += n0 * h0.y + n1 * h1.y;
            v.z += n0 * h0.z + n1 * h1.z;
            v.w += n0 * h0.w + n1 * h1.w;
            j += 2;
        }
        if (j < c) {
            int2 e = __ldg(&ed[s + j]);
            float nm = __int_as_float(e.y);
            float4 hh = bf16x4_to_f4(((const uint2*)(H + (size_t)e.x * D))[lane]);
            v.x += nm * hh.x; v.y += nm * hh.y;
            v.z += nm * hh.z; v.w += nm * hh.w;
        }
        v.x = fmaxf(fmaf(v.x, di, bb.x), 0.f);        // apply dst factor + bias
        v.y = fmaxf(fmaf(v.y, di, bb.y), 0.f);
        v.z = fmaxf(fmaf(v.z, di, bb.z), 0.f);
        v.w = fmaxf(fmaf(v.w, di, bb.w), 0.f);
        float ss = v.x * v.x + v.y * v.y + v.z * v.z + v.w * v.w;
#pragma unroll
        for (int o = 16; o; o >>= 1) ss += __shfl_xor_sync(0xFFFFFFFFu, ss, o);
        float scale = 1.0f / fmaxf(sqrtf(ss), 1e-12f);
        macc.x += v.x * scale;
        macc.y += v.y * scale;
        macc.z += v.z * scale;
        macc.w += v.w * scale;
    }
    float* so = sacc + lane * 4;
    atomicAdd(so + 0, macc.x);
    atomicAdd(so + 1, macc.y);
    atomicAdd(so + 2, macc.z);
    atomicAdd(so + 3, macc.w);
    __syncthreads();
    if (t < D) atomicAdd(accBase + t, sacc[t]);

    // ---- last block: final MLP; consumes acc then zeroes it for next replay ----
    __syncthreads();
    if (t == 0) {
        __threadfence();
        slast = (atomicAdd(done, 1) == (int)gridDim.x - 1);
    }
    __syncthreads();
    if (slast) {
        __threadfence();
        __shared__ float cvec[256];
        __shared__ float h1[64];
        cvec[t] = __ldcg(&acc[t]) * (t < 128 ? invNnet : invNdag);
        __syncthreads();
        acc[t] = 0.f;                                 // self-clean (sole reader)
        if (t < 64) {
            float s = b1[t];
#pragma unroll 8
            for (int i = 0; i < 256; i++) s += cvec[i] * W1[i * 64 + t];
            h1[t] = fmaxf(s, 0.f);
        }
        __syncthreads();
        if (t == 0) {
            float s = b2[0];
#pragma unroll
            for (int j = 0; j < 64; j++) s += h1[j] * W2[j];
            out[0] = s;
            *done = 0;                                // self-clean
        }
    }
}

// ---------------- launch ----------------------------------------------------------
extern "C" void kernel_launch(void* const* d_in, const int* in_sizes, int n_in,
                              void* d_out, int out_size) {
    const float* net_feat = (const float*)d_in[0];
    const int*   net_ei   = (const int*)  d_in[1];
    const float* net_ew   = (const float*)d_in[2];
    const float* dag_feat = (const float*)d_in[3];
    const int*   dag_ei   = (const int*)  d_in[4];
    const float* dag_ew   = (const float*)d_in[5];
    const float* W_net    = (const float*)d_in[6];
    const float* b_net    = (const float*)d_in[7];
    const float* W_dag    = (const float*)d_in[8];
    const float* b_dag    = (const float*)d_in[9];
    const float* W1       = (const float*)d_in[10];
    const float* b1       = (const float*)d_in[11];
    const float* W2       = (const float*)d_in[12];
    const float* b2       = (const float*)d_in[13];
    float* out = (float*)d_out;

    const int N_net = in_sizes[0] / D;
    const int E_net = in_sizes[2];
    const int N_dag = in_sizes[3] / D;
    const int E_dag = in_sizes[5];

    void *p;
    cudaGetSymbolAddress(&p, g_h_net);    __nv_bfloat16* h_net = (__nv_bfloat16*)p;
    cudaGetSymbolAddress(&p, g_h_dag);    __nv_bfloat16* h_dag = (__nv_bfloat16*)p;
    cudaGetSymbolAddress(&p, g_dc_net);   float2* dc_net = (float2*)p;
    cudaGetSymbolAddress(&p, g_dc_dag);   float2* dc_dag = (float2*)p;
    cudaGetSymbolAddress(&p, g_dinv_net); float* dinv_net = (float*)p;
    cudaGetSymbolAddress(&p, g_dinv_dag); float* dinv_dag = (float*)p;
    cudaGetSymbolAddress(&p, g_rs_net);   int* rs_net = (int*)p;
    cudaGetSymbolAddress(&p, g_rs_dag);   int* rs_dag = (int*)p;
    cudaGetSymbolAddress(&p, g_cnt_net);  int* cnt_net = (int*)p;
    cudaGetSymbolAddress(&p, g_cnt_dag);  int* cnt_dag = (int*)p;
    cudaGetSymbolAddress(&p, g_ptr_net);  int* ptr_net = (int*)p;
    cudaGetSymbolAddress(&p, g_ptr_dag);  int* ptr_dag = (int*)p;
    cudaGetSymbolAddress(&p, g_ed_net);   int2* ed_net = (int2*)p;
    cudaGetSymbolAddress(&p, g_ed_dag);   int2* ed_dag = (int2*)p;
    cudaGetSymbolAddress(&p, g_status_net); u64* st_net = (u64*)p;
    cudaGetSymbolAddress(&p, g_status_dag); u64* st_dag = (u64*)p;
    cudaGetSymbolAddress(&p, g_done);     int* done = (int*)p;
    cudaGetSymbolAddress(&p, g_acc);      float* acc = (float*)p;

    const int smem_gemm = 96 * 1024;
    cudaFuncSetAttribute(k_hist_gemmnet,
                         cudaFuncAttributeMaxDynamicSharedMemorySize, smem_gemm);
    cudaFuncSetAttribute(k_reorder_gemmdag,
                         cudaFuncAttributeMaxDynamicSharedMemorySize, smem_gemm);

    const int nbN = (N_net + 4095) / 4096;
    const int nbD = (N_dag + 4095) / 4096;

    // K1: histogram(both) overlapped with GEMM(net)
    const int histBlocks = 148;
    k_hist_gemmnet<<<histBlocks + (N_net + 63) / 64, 256, smem_gemm>>>(
        net_ei, net_ew, dc_net, E_net,
        dag_ei, dag_ew, dc_dag, E_dag,
        histBlocks, net_feat, W_net, h_net, N_net);

    // K2: single-pass scan (emits dinv, self-cleans dc)
    k_scan<<<nbN + nbD, 256>>>(dc_net, rs_net, cnt_net, ptr_net, dinv_net, N_net, nbN,
                               dc_dag, rs_dag, cnt_dag, ptr_dag, dinv_dag, N_dag,
                               st_net, st_dag);

    // K3: reorder(both, slim) overlapped with GEMM(dag); cleans status
    const int reorderBlocks = 148;
    k_reorder_gemmdag<<<reorderBlocks + (N_dag + 63) / 64, 256, smem_gemm>>>(
        net_ei, net_ew, dinv_net, ptr_net, ed_net, E_net,
        dag_ei, dag_ew, dinv_dag, ptr_dag, ed_dag, E_dag,
        reorderBlocks, dag_feat, W_dag, h_dag, N_dag,
        st_net, st_dag);

    // K4: gather + epilogue + final MLP (cleans acc, done)
    const int blocksNet = 540, blocksDag = 348;
    gather_kernel<<<blocksNet + blocksDag, 256>>>(
        rs_net, cnt_net, ed_net, h_net, dinv_net, b_net, N_net, blocksNet,
        rs_dag, cnt_dag, ed_dag, h_dag, dinv_dag, b_dag, N_dag, acc, done,
        W1, b1, W2, b2, 1.0f / (float)N_net, 1.0f / (float)N_dag, out);
}

// round 13
// speedup vs baseline: 1.4544x; 1.0679x over previous
#include <cuda_runtime.h>
#include <cuda_bf16.h>

#define D 128
#define MAXN_NET 100000
#define MAXN_DAG 50000
#define MAXE_NET 600000
#define MAXE_DAG 400000

typedef unsigned long long u64;
typedef unsigned int u32;

// ---------------- device scratch (allocation-free rule: __device__ globals) ---
// Self-cleaning across graph replays:
//   dc     : zeroed by scan (this replay) before hist (next replay); zero at load
//   status : zeroed by K3 block 0 (this replay) for scan (next replay)
//   done   : reset by gather's last block
//   acc    : zeroed by gather's last block AFTER consuming it (sole reader)
__device__ __align__(16) __nv_bfloat16 g_h_net[MAXN_NET * D];
__device__ __align__(16) __nv_bfloat16 g_h_dag[MAXN_DAG * D];
__device__ __align__(16) float2 g_dc_net[MAXN_NET];   // (sum ew, cnt) via RED
__device__ __align__(16) float2 g_dc_dag[MAXN_DAG];
__device__ float g_dinv_net[MAXN_NET];                 // rsqrt(deg incl self-loop)
__device__ float g_dinv_dag[MAXN_DAG];
__device__ int   g_rs_net[MAXN_NET];
__device__ int   g_rs_dag[MAXN_DAG];
__device__ int   g_cnt_net[MAXN_NET];
__device__ int   g_cnt_dag[MAXN_DAG];
__device__ int   g_ptr_net[MAXN_NET];
__device__ int   g_ptr_dag[MAXN_DAG];
__device__ __align__(16) int2 g_ed_net[MAXE_NET];     // (src, dinv[src]*ew as int)
__device__ __align__(16) int2 g_ed_dag[MAXE_DAG];
__device__ u64   g_status_net[64];                    // lookback (value<<32)|flag
__device__ u64   g_status_dag[64];
__device__ int   g_done;
__device__ __align__(16) float g_acc[2 * D];

// ---------------- helpers ------------------------------------------------------
__device__ __forceinline__ u32 pack_bf16x2(float lo, float hi) {
    __nv_bfloat162 p = __float22bfloat162_rn(make_float2(lo, hi));
    return *reinterpret_cast<u32*>(&p);
}
__device__ __forceinline__ float4 bf16x4_to_f4(uint2 u) {
    __nv_bfloat162 p0 = *reinterpret_cast<__nv_bfloat162*>(&u.x);
    __nv_bfloat162 p1 = *reinterpret_cast<__nv_bfloat162*>(&u.y);
    float2 f0 = __bfloat1622float2(p0);
    float2 f1 = __bfloat1622float2(p1);
    return make_float4(f0.x, f0.y, f1.x, f1.y);
}
__device__ __forceinline__ u32 f2tf32(float f) {
    u32 r;
    asm("cvt.rna.tf32.f32 %0, %1;" : "=r"(r) : "f"(f));
    return r;
}
__device__ __forceinline__ uint4 f4_to_tf32x4(float4 v) {
    return make_uint4(f2tf32(v.x), f2tf32(v.y), f2tf32(v.z), f2tf32(v.w));
}
__device__ __forceinline__ void ldsm_x4(u32& r0, u32& r1, u32& r2, u32& r3, u32 a) {
    asm volatile("ldmatrix.sync.aligned.m8n8.x4.shared.b16 {%0,%1,%2,%3}, [%4];"
                 : "=r"(r0), "=r"(r1), "=r"(r2), "=r"(r3) : "r"(a));
}
__device__ __forceinline__ void mma_tf32(float c[4], u32 a0, u32 a1, u32 a2, u32 a3,
                                         u32 b0, u32 b1) {
    asm volatile(
        "mma.sync.aligned.m16n8k8.row.col.f32.tf32.tf32.f32 "
        "{%0,%1,%2,%3}, {%4,%5,%6,%7}, {%8,%9}, {%0,%1,%2,%3};"
        : "+f"(c[0]), "+f"(c[1]), "+f"(c[2]), "+f"(c[3])
        : "r"(a0), "r"(a1), "r"(a2), "r"(a3), "r"(b0), "r"(b1));
}
__device__ __forceinline__ void red_add_v2(float2* p, float a, float b) {
    asm volatile("red.global.add.v2.f32 [%0], {%1,%2};"
                 :: "l"(p), "f"(a), "f"(b) : "memory");
}

// ---------------- TF32 GEMM body: 64-row tile (96KB smem, 2 blocks/SM) ---------
__device__ void gemm_body(const float* __restrict__ X, const float* __restrict__ W,
                          __nv_bfloat16* __restrict__ Hb, int N, int bid) {
    extern __shared__ char smem[];
    char* sA = smem;                 // 64 rows x 512B = 32KB
    char* sB = smem + 32 * 1024;     // 128 n-rows x 512B = 64KB (W transposed)
    const int tid = threadIdx.x;
    const int row0 = bid * 64;

    // fill Wt: transpose W[k][n] -> sB[n][k], coalesced over n
#pragma unroll
    for (int i = 0; i < 16; i++) {
        int idx = i * 256 + tid;
        int n = idx & 127, kc = idx >> 7;
        uint4 v = make_uint4(f2tf32(W[(kc * 4 + 0) * D + n]),
                             f2tf32(W[(kc * 4 + 1) * D + n]),
                             f2tf32(W[(kc * 4 + 2) * D + n]),
                             f2tf32(W[(kc * 4 + 3) * D + n]));
        *(uint4*)(sB + n * 512 + ((kc ^ (n & 7)) << 4)) = v;
    }
    // fill A (64 X rows, zero-pad past N)
#pragma unroll
    for (int i = 0; i < 8; i++) {
        int idx = i * 256 + tid;
        int r = idx >> 5, ch = idx & 31;
        int grow = row0 + r;
        float4 f = make_float4(0.f, 0.f, 0.f, 0.f);
        if (grow < N) f = ((const float4*)X)[grow * 32 + ch];
        *(uint4*)(sA + r * 512 + ((ch ^ (r & 7)) << 4)) = f4_to_tf32x4(f);
    }
    __syncthreads();

    const int lane = tid & 31;
    const int w = tid >> 5;
    const int m0 = (w >> 1) * 16;
    const int n0 = (w & 1) * 64;
    const int sub = lane >> 3, rowin = lane & 7;

    float c[8][4];
#pragma unroll
    for (int nt = 0; nt < 8; nt++)
#pragma unroll
        for (int k = 0; k < 4; k++) c[nt][k] = 0.f;

#pragma unroll
    for (int ks = 0; ks < 16; ks++) {
        u32 a[4];
        {
            int r = m0 + (sub & 1) * 8 + rowin;
            int ch = ks * 2 + (sub >> 1);
            u32 addr = (u32)__cvta_generic_to_shared(
                sA + r * 512 + ((ch ^ (r & 7)) << 4));
            ldsm_x4(a[0], a[1], a[2], a[3], addr);
        }
        u32 b[4][4];
#pragma unroll
        for (int q = 0; q < 4; q++) {
            int n = n0 + q * 16 + (sub >> 1) * 8 + rowin;
            int ch = ks * 2 + (sub & 1);
            u32 addr = (u32)__cvta_generic_to_shared(
                sB + n * 512 + ((ch ^ (n & 7)) << 4));
            ldsm_x4(b[q][0], b[q][1], b[q][2], b[q][3], addr);
        }
#pragma unroll
        for (int nt = 0; nt < 8; nt++)
            mma_tf32(c[nt], a[0], a[1], a[2], a[3],
                     b[nt >> 1][(nt & 1) * 2], b[nt >> 1][(nt & 1) * 2 + 1]);
    }

#pragma unroll
    for (int nt = 0; nt < 8; nt++) {
        int r = m0 + (lane >> 2);
        int col = n0 + nt * 8 + (lane & 3) * 2;
        int g0 = row0 + r, g1 = g0 + 8;
        if (g0 < N)
            *(u32*)(Hb + (size_t)g0 * D + col) = pack_bf16x2(c[nt][0], c[nt][1]);
        if (g1 < N)
            *(u32*)(Hb + (size_t)g1 * D + col) = pack_bf16x2(c[nt][2], c[nt][3]);
    }
}

// ---------------- K1: hist(both) + GEMM(net), overlapped -----------------------
__global__ void __launch_bounds__(256, 2)
k_hist_gemmnet(const int* __restrict__ ei_n, const float* __restrict__ ew_n,
               float2* __restrict__ dc_n, int En,
               const int* __restrict__ ei_d, const float* __restrict__ ew_d,
               float2* __restrict__ dc_d, int Ed,
               int histBlocks,
               const float* __restrict__ X, const float* __restrict__ W,
               __nv_bfloat16* __restrict__ Hb, int N) {
    if ((int)blockIdx.x < histBlocks) {
        int stride = histBlocks * 256;
        int total = En + Ed;
        for (int i = blockIdx.x * 256 + threadIdx.x; i < total; i += stride) {
            if (i < En) {
                red_add_v2(&dc_n[ei_n[En + i]], ew_n[i], 1.0f);
            } else {
                int e = i - En;
                red_add_v2(&dc_d[ei_d[Ed + e]], ew_d[e], 1.0f);
            }
        }
    } else {
        gemm_body(X, W, Hb, N, blockIdx.x - histBlocks);
    }
}

// ---------------- K2: single-pass scan; emits dinv; self-cleans dc --------------
__global__ void k_scan(float2* __restrict__ dc_n, int* __restrict__ rs_n,
                       int* __restrict__ cnt_n, int* __restrict__ ptr_n,
                       float* __restrict__ dinv_n, int Nn, int nbN,
                       float2* __restrict__ dc_d, int* __restrict__ rs_d,
                       int* __restrict__ cnt_d, int* __restrict__ ptr_d,
                       float* __restrict__ dinv_d, int Nd,
                       u64* st_n, u64* st_d) {
    float2* dc; int* rs; int* cnto; int* ptr; float* dinv; int N, blk;
    volatile u64* st;
    if ((int)blockIdx.x < nbN) {
        dc = dc_n; rs = rs_n; cnto = cnt_n; ptr = ptr_n; dinv = dinv_n;
        N = Nn; blk = blockIdx.x; st = (volatile u64*)st_n;
    } else {
        dc = dc_d; rs = rs_d; cnto = cnt_d; ptr = ptr_d; dinv = dinv_d;
        N = Nd; blk = blockIdx.x - nbN; st = (volatile u64*)st_d;
    }

    int t = threadIdx.x;
    int base = blk * 4096 + t * 16;
    int v[16], s = 0;
    float dx[16];
#pragma unroll
    for (int j = 0; j < 16; j++) {
        int idx = base + j;
        float2 d = (idx < N) ? dc[idx] : make_float2(0.f, 0.f);
        v[j] = (int)d.y;
        dx[j] = d.x;
        s += v[j];
    }
    int lane = t & 31, wid = t >> 5;
    int x = s;
#pragma unroll
    for (int o = 1; o < 32; o <<= 1) {
        int y = __shfl_up_sync(0xFFFFFFFFu, x, o);
        if (lane >= o) x += y;
    }
    __shared__ int wt[8];
    __shared__ int sprefix;
    if (lane == 31) wt[wid] = x;
    __syncthreads();
    if (t < 8) {
        int y = wt[t];
#pragma unroll
        for (int o = 1; o < 8; o <<= 1) {
            int z = __shfl_up_sync(0xFFu, y, o);
            if (t >= o) y += z;
        }
        wt[t] = y;
    }
    __syncthreads();
    int total = wt[7];
    int excl = x - s + (wid ? wt[wid - 1] : 0);

    if (t == 0) {
        if (blk == 0) { st[0] = ((u64)(u32)total << 32) | 2ull; sprefix = 0; }
        else          st[blk] = ((u64)(u32)total << 32) | 1ull;
    }
    if (blk > 0 && t < 32) {
        int running = 0;
        int end = blk;
        while (true) {
            int p = end - 1 - t;
            int f = 0, val = 0;
            if (p >= 0) {
                u64 pk;
                do { pk = st[p]; } while ((pk & 3ull) == 0ull);
                f = (int)(pk & 3ull);
                val = (int)(pk >> 32);
            }
            unsigned m2 = __ballot_sync(0xFFFFFFFFu, p >= 0 && f == 2);
            int contrib;
            bool fin;
            if (m2) {
                int l2 = __ffs(m2) - 1;
                contrib = (t <= l2 && p >= 0) ? val : 0;
                fin = true;
            } else {
                contrib = (p >= 0) ? val : 0;
                fin = false;
            }
#pragma unroll
            for (int o = 16; o; o >>= 1)
                contrib += __shfl_xor_sync(0xFFFFFFFFu, contrib, o);
            running += contrib;
            if (fin) break;
            end -= 32;
            if (end <= 0) break;
        }
        if (t == 0) {
            sprefix = running;
            st[blk] = ((u64)(u32)(running + total) << 32) | 2ull;
        }
    }
    __syncthreads();
    int run = sprefix + excl;
#pragma unroll
    for (int j = 0; j < 16; j++) {
        int idx = base + j;
        if (idx < N) {
            rs[idx] = run;
            cnto[idx] = v[j];
            ptr[idx] = run;
            dinv[idx] = rsqrtf(dx[j] + 1.0f);          // self-loop folded
            dc[idx] = make_float2(0.f, 0.f);           // self-clean
        }
        run += v[j];
    }
}

// ---------------- K3: reorder(both, slim) + GEMM(dag), overlapped ---------------
__global__ void __launch_bounds__(256, 2)
k_reorder_gemmdag(const int* __restrict__ ei_n, const float* __restrict__ ew_n,
                  const float* __restrict__ dinv_n, int* __restrict__ ptr_n,
                  int2* __restrict__ ed_n, int En,
                  const int* __restrict__ ei_d, const float* __restrict__ ew_d,
                  const float* __restrict__ dinv_d, int* __restrict__ ptr_d,
                  int2* __restrict__ ed_d, int Ed,
                  int reorderBlocks,
                  const float* __restrict__ X, const float* __restrict__ W,
                  __nv_bfloat16* __restrict__ Hb, int N,
                  u64* st_n, u64* st_d) {
    if ((int)blockIdx.x < reorderBlocks) {
        if (blockIdx.x == 0 && threadIdx.x < 128) {    // clean lookback state
            if (threadIdx.x < 64) st_n[threadIdx.x] = 0ull;
            else                  st_d[threadIdx.x - 64] = 0ull;
        }
        int stride = reorderBlocks * 256;
        int total = En + Ed;
        for (int i = blockIdx.x * 256 + threadIdx.x; i < total; i += stride) {
            const int* ei; const float* ew; const float* dinv; int* ptr;
            int2* ed; int E, e;
            if (i < En) { ei = ei_n; ew = ew_n; dinv = dinv_n; ptr = ptr_n; ed = ed_n; E = En; e = i; }
            else        { ei = ei_d; ew = ew_d; dinv = dinv_d; ptr = ptr_d; ed = ed_d; E = Ed; e = i - En; }
            int src = ei[e];
            int dst = ei[E + e];
            float nm = dinv[src] * ew[e];              // dst factor applied in gather
            int p = atomicAdd(&ptr[dst], 1);
            ed[p] = make_int2(src, __float_as_int(nm));
        }
    } else {
        gemm_body(X, W, Hb, N, blockIdx.x - reorderBlocks);
    }
}

// ---------------- K4: gather + epilogue + (last block) final MLP ----------------
// Grid sized to exactly one resident wave: 4 blocks/SM x 148 SMs = 592 blocks.
__global__ void __launch_bounds__(256, 4)
gather_kernel(const int* __restrict__ rs_n, const int* __restrict__ cnt_n,
              const int2* __restrict__ ed_n,
              const __nv_bfloat16* __restrict__ Hn,
              const float* __restrict__ dinv_n,
              const float* __restrict__ b_n, int Nn, int blocksNet,
              const int* __restrict__ rs_d, const int* __restrict__ cnt_d,
              const int2* __restrict__ ed_d,
              const __nv_bfloat16* __restrict__ Hd,
              const float* __restrict__ dinv_d,
              const float* __restrict__ b_d,  int Nd,
              float* __restrict__ acc, int* __restrict__ done,
              const float* __restrict__ W1, const float* __restrict__ b1,
              const float* __restrict__ W2, const float* __restrict__ b2,
              float invNnet, float invNdag, float* __restrict__ out) {
    bool isNet = (int)blockIdx.x < blocksNet;
    const int* rs   = isNet ? rs_n  : rs_d;
    const int* cnt  = isNet ? cnt_n : cnt_d;
    const int2* ed  = isNet ? ed_n  : ed_d;
    const __nv_bfloat16* H = isNet ? Hn : Hd;
    const float* dinv = isNet ? dinv_n : dinv_d;
    const float* bia = isNet ? b_n : b_d;
    int N = isNet ? Nn : Nd;
    float* accBase = isNet ? acc : acc + D;
    int blk  = isNet ? blockIdx.x : blockIdx.x - blocksNet;
    int nblk = isNet ? blocksNet : gridDim.x - blocksNet;

    __shared__ float sacc[D];
    __shared__ int slast;
    int t = threadIdx.x;
    if (t < D) sacc[t] = 0.f;
    __syncthreads();

    int lane = t & 31;
    int warp = blk * 8 + (t >> 5);
    int nwarps = nblk * 8;
    float4 bb = ((const float4*)bia)[lane];
    float4 macc = make_float4(0.f, 0.f, 0.f, 0.f);

    for (int i = warp; i < N; i += nwarps) {
        float di = dinv[i];
        // v accumulates di*h_i + sum(nm_e * h_src); final scale by di.
        float4 v = bf16x4_to_f4(((const uint2*)(H + (size_t)i * D))[lane]);
        v.x *= di; v.y *= di; v.z *= di; v.w *= di;
        int s = rs[i];
        int c = cnt[i];
        int j = 0;
        if (c >= 4) {                                 // pipelined 4-edge batches
            int2 e0 = __ldg(&ed[s + 0]);
            int2 e1 = __ldg(&ed[s + 1]);
            int2 e2 = __ldg(&ed[s + 2]);
            int2 e3 = __ldg(&ed[s + 3]);
            while (true) {
                float4 h0 = bf16x4_to_f4(((const uint2*)(H + (size_t)e0.x * D))[lane]);
                float4 h1 = bf16x4_to_f4(((const uint2*)(H + (size_t)e1.x * D))[lane]);
                float4 h2 = bf16x4_to_f4(((const uint2*)(H + (size_t)e2.x * D))[lane]);
                float4 h3 = bf16x4_to_f4(((const uint2*)(H + (size_t)e3.x * D))[lane]);
                float n0 = __int_as_float(e0.y), n1 = __int_as_float(e1.y);
                float n2 = __int_as_float(e2.y), n3 = __int_as_float(e3.y);
                int jn = j + 4;
                bool more = (jn + 4 <= c);
                if (more) {                           // prefetch next batch
                    e0 = __ldg(&ed[s + jn + 0]);
                    e1 = __ldg(&ed[s + jn + 1]);
                    e2 = __ldg(&ed[s + jn + 2]);
                    e3 = __ldg(&ed[s + jn + 3]);
                }
                v.x += n0 * h0.x + n1 * h1.x + n2 * h2.x + n3 * h3.x;
                v.y += n0 * h0.y + n1 * h1.y + n2 * h2.y + n3 * h3.y;
                v.z += n0 * h0.z + n1 * h1.z + n2 * h2.z + n3 * h3.z;
                v.w += n0 * h0.w + n1 * h1.w + n2 * h2.w + n3 * h3.w;
                j = jn;
                if (!more) break;
            }
        }
        if (j + 2 <= c) {
            int2 e0 = __ldg(&ed[s + j]);
            int2 e1 = __ldg(&ed[s + j + 1]);
            float4 h0 = bf16x4_to_f4(((const uint2*)(H + (size_t)e0.x * D))[lane]);
            float4 h1 = bf16x4_to_f4(((const uint2*)(H + (size_t)e1.x * D))[lane]);
            float n0 = __int_as_float(e0.y), n1 = __int_as_float(e1.y);
            v.x += n0 * h0.x + n1 * h1.x;
            v.y += n0 * h0.y + n1 * h1.y;
            v.z += n0 * h0.z + n1 * h1.z;
            v.w += n0 * h0.w + n1 * h1.w;
            j += 2;
        }
        if (j < c) {
            int2 e = __ldg(&ed[s + j]);
            float nm = __int_as_float(e.y);
            float4 hh = bf16x4_to_f4(((const uint2*)(H + (size_t)e.x * D))[lane]);
            v.x += nm * hh.x; v.y += nm * hh.y;
            v.z += nm * hh.z; v.w += nm * hh.w;
        }
        v.x = fmaxf(fmaf(v.x, di, bb.x), 0.f);        // apply dst factor + bias
        v.y = fmaxf(fmaf(v.y, di, bb.y), 0.f);
        v.z = fmaxf(fmaf(v.z, di, bb.z), 0.f);
        v.w = fmaxf(fmaf(v.w, di, bb.w), 0.f);
        float ss = v.x * v.x + v.y * v.y + v.z * v.z + v.w * v.w;
#pragma unroll
        for (int o = 16; o; o >>= 1) ss += __shfl_xor_sync(0xFFFFFFFFu, ss, o);
        float scale = 1.0f / fmaxf(sqrtf(ss), 1e-12f);
        macc.x += v.x * scale;
        macc.y += v.y * scale;
        macc.z += v.z * scale;
        macc.w += v.w * scale;
    }
    float* so = sacc + lane * 4;
    atomicAdd(so + 0, macc.x);
    atomicAdd(so + 1, macc.y);
    atomicAdd(so + 2, macc.z);
    atomicAdd(so + 3, macc.w);
    __syncthreads();
    if (t < D) atomicAdd(accBase + t, sacc[t]);

    // ---- last block: final MLP; consumes acc then zeroes it for next replay ----
    __syncthreads();
    if (t == 0) {
        __threadfence();
        slast = (atomicAdd(done, 1) == (int)gridDim.x - 1);
    }
    __syncthreads();
    if (slast) {
        __threadfence();
        __shared__ float cvec[256];
        __shared__ float h1[64];
        cvec[t] = __ldcg(&acc[t]) * (t < 128 ? invNnet : invNdag);
        __syncthreads();
        acc[t] = 0.f;                                 // self-clean (sole reader)
        if (t < 64) {
            float s = b1[t];
#pragma unroll 8
            for (int i = 0; i < 256; i++) s += cvec[i] * W1[i * 64 + t];
            h1[t] = fmaxf(s, 0.f);
        }
        __syncthreads();
        if (t == 0) {
            float s = b2[0];
#pragma unroll
            for (int j = 0; j < 64; j++) s += h1[j] * W2[j];
            out[0] = s;
            *done = 0;                                // self-clean
        }
    }
}

// ---------------- launch ----------------------------------------------------------
extern "C" void kernel_launch(void* const* d_in, const int* in_sizes, int n_in,
                              void* d_out, int out_size) {
    const float* net_feat = (const float*)d_in[0];
    const int*   net_ei   = (const int*)  d_in[1];
    const float* net_ew   = (const float*)d_in[2];
    const float* dag_feat = (const float*)d_in[3];
    const int*   dag_ei   = (const int*)  d_in[4];
    const float* dag_ew   = (const float*)d_in[5];
    const float* W_net    = (const float*)d_in[6];
    const float* b_net    = (const float*)d_in[7];
    const float* W_dag    = (const float*)d_in[8];
    const float* b_dag    = (const float*)d_in[9];
    const float* W1       = (const float*)d_in[10];
    const float* b1       = (const float*)d_in[11];
    const float* W2       = (const float*)d_in[12];
    const float* b2       = (const float*)d_in[13];
    float* out = (float*)d_out;

    const int N_net = in_sizes[0] / D;
    const int E_net = in_sizes[2];
    const int N_dag = in_sizes[3] / D;
    const int E_dag = in_sizes[5];

    void *p;
    cudaGetSymbolAddress(&p, g_h_net);    __nv_bfloat16* h_net = (__nv_bfloat16*)p;
    cudaGetSymbolAddress(&p, g_h_dag);    __nv_bfloat16* h_dag = (__nv_bfloat16*)p;
    cudaGetSymbolAddress(&p, g_dc_net);   float2* dc_net = (float2*)p;
    cudaGetSymbolAddress(&p, g_dc_dag);   float2* dc_dag = (float2*)p;
    cudaGetSymbolAddress(&p, g_dinv_net); float* dinv_net = (float*)p;
    cudaGetSymbolAddress(&p, g_dinv_dag); float* dinv_dag = (float*)p;
    cudaGetSymbolAddress(&p, g_rs_net);   int* rs_net = (int*)p;
    cudaGetSymbolAddress(&p, g_rs_dag);   int* rs_dag = (int*)p;
    cudaGetSymbolAddress(&p, g_cnt_net);  int* cnt_net = (int*)p;
    cudaGetSymbolAddress(&p, g_cnt_dag);  int* cnt_dag = (int*)p;
    cudaGetSymbolAddress(&p, g_ptr_net);  int* ptr_net = (int*)p;
    cudaGetSymbolAddress(&p, g_ptr_dag);  int* ptr_dag = (int*)p;
    cudaGetSymbolAddress(&p, g_ed_net);   int2* ed_net = (int2*)p;
    cudaGetSymbolAddress(&p, g_ed_dag);   int2* ed_dag = (int2*)p;
    cudaGetSymbolAddress(&p, g_status_net); u64* st_net = (u64*)p;
    cudaGetSymbolAddress(&p, g_status_dag); u64* st_dag = (u64*)p;
    cudaGetSymbolAddress(&p, g_done);     int* done = (int*)p;
    cudaGetSymbolAddress(&p, g_acc);      float* acc = (float*)p;

    const int smem_gemm = 96 * 1024;
    cudaFuncSetAttribute(k_hist_gemmnet,
                         cudaFuncAttributeMaxDynamicSharedMemorySize, smem_gemm);
    cudaFuncSetAttribute(k_reorder_gemmdag,
                         cudaFuncAttributeMaxDynamicSharedMemorySize, smem_gemm);

    const int nbN = (N_net + 4095) / 4096;
    const int nbD = (N_dag + 4095) / 4096;

    // K1: histogram(both) overlapped with GEMM(net)
    const int histBlocks = 148;
    k_hist_gemmnet<<<histBlocks + (N_net + 63) / 64, 256, smem_gemm>>>(
        net_ei, net_ew, dc_net, E_net,
        dag_ei, dag_ew, dc_dag, E_dag,
        histBlocks, net_feat, W_net, h_net, N_net);

    // K2: single-pass scan (emits dinv, self-cleans dc)
    k_scan<<<nbN + nbD, 256>>>(dc_net, rs_net, cnt_net, ptr_net, dinv_net, N_net, nbN,
                               dc_dag, rs_dag, cnt_dag, ptr_dag, dinv_dag, N_dag,
                               st_net, st_dag);

    // K3: reorder(both, slim) overlapped with GEMM(dag); cleans status
    const int reorderBlocks = 148;
    k_reorder_gemmdag<<<reorderBlocks + (N_dag + 63) / 64, 256, smem_gemm>>>(
        net_ei, net_ew, dinv_net, ptr_net, ed_net, E_net,
        dag_ei, dag_ew, dinv_dag, ptr_dag, ed_dag, E_dag,
        reorderBlocks, dag_feat, W_dag, h_dag, N_dag,
        st_net, st_dag);

    // K4: gather + epilogue + final MLP — one full wave (4 blocks/SM x 148 SMs)
    // Work split ~ proportional to (edges + 1.3*nodes) per graph.
    const int blocksNet = 362, blocksDag = 230;       // total = 592
    gather_kernel<<<blocksNet + blocksDag, 256>>>(
        rs_net, cnt_net, ed_net, h_net, dinv_net, b_net, N_net, blocksNet,
        rs_dag, cnt_dag, ed_dag, h_dag, dinv_dag, b_dag, N_dag, acc, done,
        W1, b1, W2, b2, 1.0f / (float)N_net, 1.0f / (float)N_dag, out);
}